// round 1
// baseline (speedup 1.0000x reference)
#include <cuda_runtime.h>

#define B_ 2
#define NA 32768
#define NG 32
#define NC 15
#define PI_F 3.1415926f

// ---------------- scratch (static device globals; no allocation) ----------------
__device__ float d_iou_max[B_ * NA];
__device__ int   d_iou_arg[B_ * NA];
__device__ int   d_pos[B_ * NA];
__device__ unsigned long long d_gtbest[B_ * NG];
__device__ double d_sum_cls[B_];
__device__ double d_sum_reg[B_];
__device__ int    d_numpos[B_];

// ---------------- init ----------------
__global__ void k_init() {
    int t = threadIdx.x;
    if (t < B_ * NG) d_gtbest[t] = 0ULL;
    if (t < B_) { d_sum_cls[t] = 0.0; d_sum_reg[t] = 0.0; d_numpos[t] = 0; }
}

// Sutherland-Hodgman clip of CCW quad p1 against CCW quad q2, replicating the
// reference's arithmetic exactly (denom clamp, emission order, shoelace).
__device__ __forceinline__ float quad_clip_area(
    const float* p1x, const float* p1y,
    const float* q2x, const float* q2y)
{
    float px[8], py[8];
    int n = 4;
#pragma unroll
    for (int k = 0; k < 4; k++) { px[k] = p1x[k]; py[k] = p1y[k]; }

    for (int e = 0; e < 4; e++) {
        float ax = q2x[e], ay = q2y[e];
        float bx = q2x[(e + 1) & 3], by = q2y[(e + 1) & 3];
        float dx = bx - ax, dy = by - ay;
        float nx[8], ny[8];
        int m = 0;
        for (int i = 0; i < n; i++) {
            int ni = (i + 1 < n) ? (i + 1) : 0;
            float cx = px[i], cy = py[i];
            float qx = px[ni], qy = py[ni];
            float dc = dx * (cy - ay) - dy * (cx - ax);
            float dn = dx * (qy - ay) - dy * (qx - ax);
            bool kc = (dc >= 0.0f);
            bool kn = (dn >= 0.0f);
            if (kc && m < 8) { nx[m] = cx; ny[m] = cy; m++; }
            if ((kc != kn) && m < 8) {
                float den = dc - dn;
                if (fabsf(den) < 1e-12f) den = 1e-12f;
                float t = dc / den;
                nx[m] = cx + t * (qx - cx);
                ny[m] = cy + t * (qy - cy);
                m++;
            }
        }
        n = m;
        for (int k = 0; k < m; k++) { px[k] = nx[k]; py[k] = ny[k]; }
        if (n == 0) break;
    }
    if (n < 3) return 0.0f;
    float s = 0.0f;
    for (int i = 0; i < n; i++) {
        int ni = (i + 1 < n) ? (i + 1) : 0;
        s += px[i] * py[ni] - px[ni] * py[i];
    }
    return 0.5f * fabsf(s);
}

// ---------------- K1: per-anchor IoUs, per-anchor max/argmax, per-GT packed max ----------------
__global__ void __launch_bounds__(256) k1_iou(
    const float* __restrict__ anchors, const float* __restrict__ ann)
{
    int b = blockIdx.y;
    __shared__ float sqx[NG][4], sqy[NG][4];   // gt quads (original order)
    __shared__ float ssq[NG][4];               // gt min-area squares
    __shared__ float sarea[NG];                // gt quad areas
    __shared__ int   srev[NG];                 // gt quad needs reversal for CCW
    __shared__ unsigned long long sbest[NG];

    int t = threadIdx.x;
    if (t < NG) {
        const float* gb = ann + ((size_t)b * NG + t) * 6;
        float x0 = gb[0], y0 = gb[1], x1 = gb[2], y1 = gb[3], th = gb[4];
        float cx = (x0 + x1) * 0.5f, cy = (y0 + y1) * 0.5f;
        float w = x1 - x0, h = y1 - y0;
        float ang = th * (PI_F / 180.0f);
        float c = cosf(ang), s = sinf(ang);
        const float ddx[4] = {-0.5f, 0.5f, 0.5f, -0.5f};
        const float ddy[4] = {-0.5f, -0.5f, 0.5f, 0.5f};
        float qx[4], qy[4];
#pragma unroll
        for (int k = 0; k < 4; k++) {
            qx[k] = cx + ddx[k] * w * c - ddy[k] * h * s;
            qy[k] = cy + ddx[k] * w * s + ddy[k] * h * c;
        }
        float sa = 0.0f;
#pragma unroll
        for (int k = 0; k < 4; k++) {
            int nk = (k + 1) & 3;
            sa += qx[k] * qy[nk] - qx[nk] * qy[k];
        }
        sarea[t] = 0.5f * fabsf(sa);
        srev[t] = (sa < 0.0f) ? 1 : 0;
#pragma unroll
        for (int k = 0; k < 4; k++) { sqx[t][k] = qx[k]; sqy[t][k] = qy[k]; }
        float ss = fmaxf(w, h) * 0.5f;
        ssq[t][0] = cx - ss; ssq[t][1] = cy - ss;
        ssq[t][2] = cx + ss; ssq[t][3] = cy + ss;
        sbest[t] = 0ULL;
    }
    __syncthreads();

    int i = blockIdx.x * blockDim.x + t;
    const float* ab = anchors + ((size_t)b * NA + i) * 5;
    float x0 = ab[0], y0 = ab[1], x1 = ab[2], y1 = ab[3], th = ab[4];
    float acx = (x0 + x1) * 0.5f, acy = (y0 + y1) * 0.5f;
    float aw = x1 - x0, ah = y1 - y0;
    float ang = th * (PI_F / 180.0f);
    float c = cosf(ang), s = sinf(ang);
    const float ddx[4] = {-0.5f, 0.5f, 0.5f, -0.5f};
    const float ddy[4] = {-0.5f, -0.5f, 0.5f, 0.5f};
    float aqx[4], aqy[4];
#pragma unroll
    for (int k = 0; k < 4; k++) {
        aqx[k] = acx + ddx[k] * aw * c - ddy[k] * ah * s;
        aqy[k] = acy + ddx[k] * aw * s + ddy[k] * ah * c;
    }
    float sa_a = 0.0f;
#pragma unroll
    for (int k = 0; k < 4; k++) {
        int nk = (k + 1) & 3;
        sa_a += aqx[k] * aqy[nk] - aqx[nk] * aqy[k];
    }
    float area_a = 0.5f * fabsf(sa_a);
    float p1x[4], p1y[4];  // CCW-normalized anchor quad
    bool arev = (sa_a < 0.0f);
#pragma unroll
    for (int k = 0; k < 4; k++) {
        int src = arev ? (3 - k) : k;
        p1x[k] = aqx[src]; p1y[k] = aqy[src];
    }
    // anchor min-area square
    float ssa = fmaxf(aw, ah) * 0.5f;
    float as0 = acx - ssa, as1 = acy - ssa, as2 = acx + ssa, as3 = acy + ssa;
    float area_asq = (as2 - as0) * (as3 - as1);

    float best = -1.0f;
    int barg = 0;
    for (int g = 0; g < NG; g++) {
        // axis-aligned square IoU (indicator)
        float lx = fmaxf(as0, ssq[g][0]), ly = fmaxf(as1, ssq[g][1]);
        float rx = fminf(as2, ssq[g][2]), ry = fminf(as3, ssq[g][3]);
        float iw = fmaxf(rx - lx, 0.0f), ih = fmaxf(ry - ly, 0.0f);
        float inter = iw * ih;
        float areag_sq = (ssq[g][2] - ssq[g][0]) * (ssq[g][3] - ssq[g][1]);
        float ind = inter / (area_asq + areag_sq - inter + 1e-6f);
        // point-in-quad (anchor center in gt quad)
        bool allp = true, alln = true;
#pragma unroll
        for (int k = 0; k < 4; k++) {
            int nk = (k + 1) & 3;
            float ex = sqx[g][nk] - sqx[g][k];
            float ey = sqy[g][nk] - sqy[g][k];
            float relx = acx - sqx[g][k];
            float rely = acy - sqy[g][k];
            float cr = ex * rely - ey * relx;
            allp = allp && (cr >= 0.0f);
            alln = alln && (cr <= 0.0f);
        }
        bool inside = allp || alln;

        float iou = 0.0f;
        if (inside && (ind > 0.1f)) {
            float q2x[4], q2y[4];
            int rv = srev[g];
#pragma unroll
            for (int k = 0; k < 4; k++) {
                int src = rv ? (3 - k) : k;
                q2x[k] = sqx[g][src]; q2y[k] = sqy[g][src];
            }
            float ia = quad_clip_area(p1x, p1y, q2x, q2y);
            iou = ia / (area_a + sarea[g] - ia + 1e-6f);
        }
        if (iou > best) { best = iou; barg = g; }
        unsigned long long pk =
            ((unsigned long long)__float_as_uint(iou) << 32) |
            (unsigned long long)(0xFFFFFFFFu - (unsigned)i);
        atomicMax(&sbest[g], pk);
    }

    int gi = b * NA + i;
    d_iou_max[gi] = best;
    d_iou_arg[gi] = barg;
    d_pos[gi] = (best >= 0.5f) ? 1 : 0;

    __syncthreads();
    if (t < NG) atomicMax(&d_gtbest[b * NG + t], sbest[t]);
}

// ---------------- K2: low-quality scatter (pos[argmax_gt] |= max_gt < 0.5) ----------------
__global__ void k2_scatter() {
    int t = blockIdx.x * blockDim.x + threadIdx.x;
    if (t >= B_ * NG) return;
    unsigned long long pk = d_gtbest[t];
    float mx = __uint_as_float((unsigned)(pk >> 32));
    int arg = (int)(0xFFFFFFFFu - (unsigned)(pk & 0xFFFFFFFFull));
    int b = t / NG;
    if (mx < 0.5f) atomicMax(&d_pos[b * NA + arg], 1);
}

// ---------------- K3: focal cls + smooth-L1 reg, block-reduced double sums ----------------
__global__ void __launch_bounds__(256) k3_loss(
    const float* __restrict__ cls, const float* __restrict__ reg,
    const float* __restrict__ anchors, const float* __restrict__ ann)
{
    int b = blockIdx.y;
    int t = threadIdx.x;
    int i = blockIdx.x * blockDim.x + t;
    int gi = b * NA + i;

    int p = d_pos[gi];
    float im = d_iou_max[gi];
    int arg = d_iou_arg[gi];

    const float* cr = cls + ((size_t)b * NA + i) * NC;
    float csum = 0.0f;
    float rsum = 0.0f;

    if (p) {
        const float* gb = ann + ((size_t)b * NG + arg) * 6;
        int lab = (int)gb[5];
#pragma unroll
        for (int c_ = 0; c_ < NC; c_++) {
            float x = fminf(fmaxf(cr[c_], 1e-4f), 0.9999f);
            if (c_ == lab) {
                float om = 1.0f - x;
                csum += 0.25f * om * om * (-logf(x + 1e-6f));
            } else {
                csum += 0.75f * x * x * (-logf(1.0f - x + 1e-6f));
            }
        }
        // regression target: encode(anchor, gt[arg])
        const float* ab = anchors + ((size_t)b * NA + i) * 5;
        float ax0 = ab[0], ay0 = ab[1], ax1 = ab[2], ay1 = ab[3], at = ab[4];
        float acx = (ax0 + ax1) * 0.5f, acy = (ay0 + ay1) * 0.5f;
        float aw = ax1 - ax0, ah = ay1 - ay0;
        float gx0 = gb[0], gy0 = gb[1], gx1 = gb[2], gy1 = gb[3], gth = gb[4];
        float gcx = (gx0 + gx1) * 0.5f, gcy = (gy0 + gy1) * 0.5f;
        float gw = gx1 - gx0, gh = gy1 - gy0;
        float tgt5[5];
        tgt5[0] = (gcx - acx) / aw;
        tgt5[1] = (gcy - acy) / ah;
        tgt5[2] = logf(gw / aw);
        tgt5[3] = logf(gh / ah);
        tgt5[4] = (gth - at) * (PI_F / 180.0f);
        const float* rr = reg + ((size_t)b * NA + i) * 5;
        const float beta = 1.0f / 9.0f;
#pragma unroll
        for (int k = 0; k < 5; k++) {
            float diff = fabsf(rr[k] - tgt5[k]);
            rsum += (diff < beta) ? (0.5f * diff * diff / beta) : (diff - 0.5f * beta);
        }
    } else if (im < 0.4f) {
#pragma unroll
        for (int c_ = 0; c_ < NC; c_++) {
            float x = fminf(fmaxf(cr[c_], 1e-4f), 0.9999f);
            csum += 0.75f * x * x * (-logf(1.0f - x + 1e-6f));
        }
    }
    // else (0.4 <= iou_max < 0.5, not pos): target = -1 -> contributes 0

    __shared__ double rc[256];
    __shared__ double rg[256];
    __shared__ int    rp[256];
    rc[t] = (double)csum;
    rg[t] = (double)rsum;
    rp[t] = p;
    __syncthreads();
    for (int s2 = 128; s2 > 0; s2 >>= 1) {
        if (t < s2) {
            rc[t] += rc[t + s2];
            rg[t] += rg[t + s2];
            rp[t] += rp[t + s2];
        }
        __syncthreads();
    }
    if (t == 0) {
        atomicAdd(&d_sum_cls[b], rc[0]);
        atomicAdd(&d_sum_reg[b], rg[0]);
        atomicAdd(&d_numpos[b], rp[0]);
    }
}

// ---------------- K4: finalize two scalars ----------------
__global__ void k4_final(float* __restrict__ out) {
    if (threadIdx.x == 0 && blockIdx.x == 0) {
        float lc = 0.0f, lr = 0.0f;
        for (int b = 0; b < B_; b++) {
            int np = d_numpos[b];
            float npf = (float)(np > 1 ? np : 1);
            lc += (float)d_sum_cls[b] / npf;
            lr += (np > 0) ? ((float)d_sum_reg[b] / (npf * 5.0f)) : 0.0f;
        }
        out[0] = 5.0f * (lc / (float)B_);
        out[1] = 2.0f * (lr / (float)B_);
    }
}

// ---------------- launch ----------------
extern "C" void kernel_launch(void* const* d_in, const int* in_sizes, int n_in,
                              void* d_out, int out_size) {
    const float* cls     = (const float*)d_in[0];
    const float* reg     = (const float*)d_in[1];
    const float* anchors = (const float*)d_in[2];
    const float* ann     = (const float*)d_in[3];
    float* out = (float*)d_out;

    k_init<<<1, 64>>>();
    dim3 grid(NA / 256, B_);
    k1_iou<<<grid, 256>>>(anchors, ann);
    k2_scatter<<<1, 64>>>();
    k3_loss<<<grid, 256>>>(cls, reg, anchors, ann);
    k4_final<<<1, 32>>>(out);
}

// round 2
// speedup vs baseline: 2.0971x; 2.0971x over previous
#include <cuda_runtime.h>

#define B_ 2
#define NA 32768
#define NG 32
#define NC 15
#define PI_F 3.1415926f
#define MAXPAIRS (B_ * NA * NG)

// ---------------- scratch ----------------
__device__ unsigned long long d_abest[B_ * NA];   // (iou_bits<<32)|(0xFFFFFFFF-g)
__device__ int   d_pos[B_ * NA];                  // forced-pos scatter flag (0/1)
__device__ unsigned long long d_gtbest[B_ * NG];  // (iou_bits<<32)|(0xFFFFFFFF-anchor)
__device__ unsigned d_pairs[MAXPAIRS];
__device__ int d_npairs;
__device__ double d_sum_cls[B_];
__device__ double d_sum_reg[B_];
__device__ int    d_numpos[B_];

// ---------------- init ----------------
__global__ void k_init() {
    int t = threadIdx.x;
    if (t < B_ * NG) d_gtbest[t] = 0xFFFFFFFFull;  // iou=0, anchor index 0
    if (t < B_) { d_sum_cls[t] = 0.0; d_sum_reg[t] = 0.0; d_numpos[t] = 0; }
    if (t == 0) d_npairs = 0;
}

// ---------------- helpers ----------------
__device__ __forceinline__ void make_quad(float cx, float cy, float w, float h,
                                          float th_deg, float* qx, float* qy,
                                          float* signed_area) {
    float ang = th_deg * (PI_F / 180.0f);
    float c = cosf(ang), s = sinf(ang);
    const float ddx[4] = {-0.5f, 0.5f, 0.5f, -0.5f};
    const float ddy[4] = {-0.5f, -0.5f, 0.5f, 0.5f};
#pragma unroll
    for (int k = 0; k < 4; k++) {
        qx[k] = cx + ddx[k] * w * c - ddy[k] * h * s;
        qy[k] = cy + ddx[k] * w * s + ddy[k] * h * c;
    }
    float sa = 0.0f;
#pragma unroll
    for (int k = 0; k < 4; k++) {
        int nk = (k + 1) & 3;
        sa += qx[k] * qy[nk] - qx[nk] * qy[k];
    }
    *signed_area = sa;
}

// Sutherland-Hodgman clip of CCW quad p1 against CCW quad q2 (reference-exact).
__device__ float quad_clip_area(const float* p1x, const float* p1y,
                                const float* q2x, const float* q2y)
{
    float px[8], py[8];
    int n = 4;
#pragma unroll
    for (int k = 0; k < 4; k++) { px[k] = p1x[k]; py[k] = p1y[k]; }

    for (int e = 0; e < 4; e++) {
        float ax = q2x[e], ay = q2y[e];
        float bx = q2x[(e + 1) & 3], by = q2y[(e + 1) & 3];
        float dx = bx - ax, dy = by - ay;
        float nx[8], ny[8];
        int m = 0;
        for (int i = 0; i < n; i++) {
            int ni = (i + 1 < n) ? (i + 1) : 0;
            float cx = px[i], cy = py[i];
            float qx = px[ni], qy = py[ni];
            float dc = dx * (cy - ay) - dy * (cx - ax);
            float dn = dx * (qy - ay) - dy * (qx - ax);
            bool kc = (dc >= 0.0f);
            bool kn = (dn >= 0.0f);
            if (kc && m < 8) { nx[m] = cx; ny[m] = cy; m++; }
            if ((kc != kn) && m < 8) {
                float den = dc - dn;
                if (fabsf(den) < 1e-12f) den = 1e-12f;
                float t = dc / den;
                nx[m] = cx + t * (qx - cx);
                ny[m] = cy + t * (qy - cy);
                m++;
            }
        }
        n = m;
        for (int k = 0; k < m; k++) { px[k] = nx[k]; py[k] = ny[k]; }
        if (n == 0) break;
    }
    if (n < 3) return 0.0f;
    float s = 0.0f;
    for (int i = 0; i < n; i++) {
        int ni = (i + 1 < n) ? (i + 1) : 0;
        s += px[i] * py[ni] - px[ni] * py[i];
    }
    return 0.5f * fabsf(s);
}

// ---------------- A: cheap gates + pair compaction ----------------
__global__ void __launch_bounds__(256) kA_gate(
    const float* __restrict__ anchors, const float* __restrict__ ann)
{
    int b = blockIdx.y;
    __shared__ float sqx[NG][4], sqy[NG][4];
    __shared__ float ssq[NG][4];

    int t = threadIdx.x;
    if (t < NG) {
        const float* gb = ann + ((size_t)b * NG + t) * 6;
        float x0 = gb[0], y0 = gb[1], x1 = gb[2], y1 = gb[3], th = gb[4];
        float cx = (x0 + x1) * 0.5f, cy = (y0 + y1) * 0.5f;
        float w = x1 - x0, h = y1 - y0;
        float qx[4], qy[4], sa;
        make_quad(cx, cy, w, h, th, qx, qy, &sa);
#pragma unroll
        for (int k = 0; k < 4; k++) { sqx[t][k] = qx[k]; sqy[t][k] = qy[k]; }
        float ss = fmaxf(w, h) * 0.5f;
        ssq[t][0] = cx - ss; ssq[t][1] = cy - ss;
        ssq[t][2] = cx + ss; ssq[t][3] = cy + ss;
    }
    __syncthreads();

    int i = blockIdx.x * blockDim.x + t;
    const float* ab = anchors + ((size_t)b * NA + i) * 5;
    float x0 = ab[0], y0 = ab[1], x1 = ab[2], y1 = ab[3];
    float acx = (x0 + x1) * 0.5f, acy = (y0 + y1) * 0.5f;
    float aw = x1 - x0, ah = y1 - y0;
    float ssa = fmaxf(aw, ah) * 0.5f;
    float as0 = acx - ssa, as1 = acy - ssa, as2 = acx + ssa, as3 = acy + ssa;
    float area_asq = (as2 - as0) * (as3 - as1);

    unsigned mask = 0;
#pragma unroll 4
    for (int g = 0; g < NG; g++) {
        float lx = fmaxf(as0, ssq[g][0]), ly = fmaxf(as1, ssq[g][1]);
        float rx = fminf(as2, ssq[g][2]), ry = fminf(as3, ssq[g][3]);
        float iw = fmaxf(rx - lx, 0.0f), ih = fmaxf(ry - ly, 0.0f);
        float inter = iw * ih;
        float areag_sq = (ssq[g][2] - ssq[g][0]) * (ssq[g][3] - ssq[g][1]);
        float ind = inter / (area_asq + areag_sq - inter + 1e-6f);

        bool allp = true, alln = true;
#pragma unroll
        for (int k = 0; k < 4; k++) {
            int nk = (k + 1) & 3;
            float ex = sqx[g][nk] - sqx[g][k];
            float ey = sqy[g][nk] - sqy[g][k];
            float cr = ex * (acy - sqy[g][k]) - ey * (acx - sqx[g][k]);
            allp = allp && (cr >= 0.0f);
            alln = alln && (cr <= 0.0f);
        }
        if ((allp || alln) && (ind > 0.1f)) mask |= (1u << g);
    }

    int gi = b * NA + i;
    d_abest[gi] = 0xFFFFFFFFull;  // iou=0, g=0
    d_pos[gi] = 0;

    // warp-aggregated compaction
    int lane = t & 31;
    int cnt = __popc(mask);
    int acc = cnt;
#pragma unroll
    for (int off = 1; off < 32; off <<= 1) {
        int v = __shfl_up_sync(0xFFFFFFFFu, acc, off);
        if (lane >= off) acc += v;
    }
    int excl = acc - cnt;
    int total = __shfl_sync(0xFFFFFFFFu, acc, 31);
    int base = 0;
    if (lane == 31 && total > 0) base = atomicAdd(&d_npairs, total);
    base = __shfl_sync(0xFFFFFFFFu, base, 31);
    int p = base + excl;
    unsigned m = mask;
    while (m) {
        int g = __ffs(m) - 1;
        m &= m - 1;
        d_pairs[p++] = ((unsigned)b << 20) | ((unsigned)i << 5) | (unsigned)g;
    }
}

// ---------------- B: clip only gated pairs ----------------
__global__ void __launch_bounds__(256) kB_clip(
    const float* __restrict__ anchors, const float* __restrict__ ann)
{
    int npairs = d_npairs;
    for (int idx = blockIdx.x * blockDim.x + threadIdx.x; idx < npairs;
         idx += gridDim.x * blockDim.x) {
        unsigned pr = d_pairs[idx];
        int g = pr & 31;
        int i = (pr >> 5) & 32767;
        int b = pr >> 20;

        const float* ab = anchors + ((size_t)b * NA + i) * 5;
        float ax0 = ab[0], ay0 = ab[1], ax1 = ab[2], ay1 = ab[3], ath = ab[4];
        float acx = (ax0 + ax1) * 0.5f, acy = (ay0 + ay1) * 0.5f;
        float aw = ax1 - ax0, ah = ay1 - ay0;
        float aqx[4], aqy[4], sa_a;
        make_quad(acx, acy, aw, ah, ath, aqx, aqy, &sa_a);
        float area_a = 0.5f * fabsf(sa_a);
        float p1x[4], p1y[4];
        bool arev = (sa_a < 0.0f);
#pragma unroll
        for (int k = 0; k < 4; k++) {
            int src = arev ? (3 - k) : k;
            p1x[k] = aqx[src]; p1y[k] = aqy[src];
        }

        const float* gb = ann + ((size_t)b * NG + g) * 6;
        float gx0 = gb[0], gy0 = gb[1], gx1 = gb[2], gy1 = gb[3], gth = gb[4];
        float gcx = (gx0 + gx1) * 0.5f, gcy = (gy0 + gy1) * 0.5f;
        float gw = gx1 - gx0, gh = gy1 - gy0;
        float gqx[4], gqy[4], sa_g;
        make_quad(gcx, gcy, gw, gh, gth, gqx, gqy, &sa_g);
        float area_g = 0.5f * fabsf(sa_g);
        float q2x[4], q2y[4];
        bool grev = (sa_g < 0.0f);
#pragma unroll
        for (int k = 0; k < 4; k++) {
            int src = grev ? (3 - k) : k;
            q2x[k] = gqx[src]; q2y[k] = gqy[src];
        }

        float ia = quad_clip_area(p1x, p1y, q2x, q2y);
        float iou = ia / (area_a + area_g - ia + 1e-6f);

        unsigned bits = __float_as_uint(iou);
        atomicMax(&d_abest[b * NA + i],
                  ((unsigned long long)bits << 32) |
                  (unsigned long long)(0xFFFFFFFFu - (unsigned)g));
        atomicMax(&d_gtbest[b * NG + g],
                  ((unsigned long long)bits << 32) |
                  (unsigned long long)(0xFFFFFFFFu - (unsigned)i));
    }
}

// ---------------- K2: low-quality scatter ----------------
__global__ void k2_scatter() {
    int t = blockIdx.x * blockDim.x + threadIdx.x;
    if (t >= B_ * NG) return;
    unsigned long long pk = d_gtbest[t];
    float mx = __uint_as_float((unsigned)(pk >> 32));
    int arg = (int)(0xFFFFFFFFu - (unsigned)(pk & 0xFFFFFFFFull));
    int b = t / NG;
    if (mx < 0.5f) d_pos[b * NA + arg] = 1;
}

// ---------------- K3: focal cls + smooth-L1 reg ----------------
__global__ void __launch_bounds__(256) k3_loss(
    const float* __restrict__ cls, const float* __restrict__ reg,
    const float* __restrict__ anchors, const float* __restrict__ ann)
{
    int b = blockIdx.y;
    int t = threadIdx.x;
    int i = blockIdx.x * blockDim.x + t;
    int gi = b * NA + i;

    unsigned long long pk = d_abest[gi];
    float im = __uint_as_float((unsigned)(pk >> 32));
    int arg = (int)(0xFFFFFFFFu - (unsigned)(pk & 0xFFFFFFFFull));
    int p = (im >= 0.5f) || d_pos[gi];

    const float* cr = cls + ((size_t)b * NA + i) * NC;
    float csum = 0.0f;
    float rsum = 0.0f;

    if (p) {
        const float* gb = ann + ((size_t)b * NG + arg) * 6;
        int lab = (int)gb[5];
#pragma unroll
        for (int c_ = 0; c_ < NC; c_++) {
            float x = fminf(fmaxf(cr[c_], 1e-4f), 0.9999f);
            if (c_ == lab) {
                float om = 1.0f - x;
                csum += 0.25f * om * om * (-__logf(x + 1e-6f));
            } else {
                csum += 0.75f * x * x * (-__logf(1.0f - x + 1e-6f));
            }
        }
        const float* ab = anchors + ((size_t)b * NA + i) * 5;
        float ax0 = ab[0], ay0 = ab[1], ax1 = ab[2], ay1 = ab[3], at = ab[4];
        float acx = (ax0 + ax1) * 0.5f, acy = (ay0 + ay1) * 0.5f;
        float aw = ax1 - ax0, ah = ay1 - ay0;
        float gx0 = gb[0], gy0 = gb[1], gx1 = gb[2], gy1 = gb[3], gth = gb[4];
        float gcx = (gx0 + gx1) * 0.5f, gcy = (gy0 + gy1) * 0.5f;
        float gw = gx1 - gx0, gh = gy1 - gy0;
        float tgt5[5];
        tgt5[0] = (gcx - acx) / aw;
        tgt5[1] = (gcy - acy) / ah;
        tgt5[2] = logf(gw / aw);
        tgt5[3] = logf(gh / ah);
        tgt5[4] = (gth - at) * (PI_F / 180.0f);
        const float* rr = reg + ((size_t)b * NA + i) * 5;
        const float beta = 1.0f / 9.0f;
#pragma unroll
        for (int k = 0; k < 5; k++) {
            float diff = fabsf(rr[k] - tgt5[k]);
            rsum += (diff < beta) ? (0.5f * diff * diff / beta) : (diff - 0.5f * beta);
        }
    } else if (im < 0.4f) {
#pragma unroll
        for (int c_ = 0; c_ < NC; c_++) {
            float x = fminf(fmaxf(cr[c_], 1e-4f), 0.9999f);
            csum += 0.75f * x * x * (-__logf(1.0f - x + 1e-6f));
        }
    }

    __shared__ double rc[256];
    __shared__ double rg[256];
    __shared__ int    rp[256];
    rc[t] = (double)csum;
    rg[t] = (double)rsum;
    rp[t] = p;
    __syncthreads();
    for (int s2 = 128; s2 > 0; s2 >>= 1) {
        if (t < s2) {
            rc[t] += rc[t + s2];
            rg[t] += rg[t + s2];
            rp[t] += rp[t + s2];
        }
        __syncthreads();
    }
    if (t == 0) {
        atomicAdd(&d_sum_cls[b], rc[0]);
        atomicAdd(&d_sum_reg[b], rg[0]);
        atomicAdd(&d_numpos[b], rp[0]);
    }
}

// ---------------- K4: finalize ----------------
__global__ void k4_final(float* __restrict__ out) {
    if (threadIdx.x == 0 && blockIdx.x == 0) {
        float lc = 0.0f, lr = 0.0f;
        for (int b = 0; b < B_; b++) {
            int np = d_numpos[b];
            float npf = (float)(np > 1 ? np : 1);
            lc += (float)d_sum_cls[b] / npf;
            lr += (np > 0) ? ((float)d_sum_reg[b] / (npf * 5.0f)) : 0.0f;
        }
        out[0] = 5.0f * (lc / (float)B_);
        out[1] = 2.0f * (lr / (float)B_);
    }
}

// ---------------- launch ----------------
extern "C" void kernel_launch(void* const* d_in, const int* in_sizes, int n_in,
                              void* d_out, int out_size) {
    const float* cls     = (const float*)d_in[0];
    const float* reg     = (const float*)d_in[1];
    const float* anchors = (const float*)d_in[2];
    const float* ann     = (const float*)d_in[3];
    float* out = (float*)d_out;

    k_init<<<1, 64>>>();
    dim3 grid(NA / 256, B_);
    kA_gate<<<grid, 256>>>(anchors, ann);
    kB_clip<<<256, 256>>>(anchors, ann);
    k2_scatter<<<1, 64>>>();
    k3_loss<<<grid, 256>>>(cls, reg, anchors, ann);
    k4_final<<<1, 32>>>(out);
}

// round 3
// speedup vs baseline: 2.6189x; 1.2489x over previous
#include <cuda_runtime.h>

#define B_ 2
#define NA 32768
#define NG 32
#define NC 15
#define PI_F 3.1415926f
#define NBLKX (NA / 256)
#define TOTBLK (NBLKX * B_)

// ---------------- scratch (static init = state for first call; last block of kL resets for replays) ----------------
#define F4 0xFFFFFFFFull,0xFFFFFFFFull,0xFFFFFFFFull,0xFFFFFFFFull
#define F16 F4,F4,F4,F4
__device__ unsigned long long d_gtbest[B_ * NG] = {F16, F16, F16, F16};  // (iou<<32)|(~anchor): iou=0,anchor=0
__device__ unsigned long long d_abest[B_ * NA];       // fully rewritten by kA each call
__device__ double d_sum_cls[B_];                      // zero-init; reset by kL
__device__ double d_sum_reg[B_];
__device__ int    d_numpos[B_];
__device__ int    d_done;

// ---------------- helpers ----------------
__device__ __forceinline__ void make_quad(float cx, float cy, float w, float h,
                                          float th_deg, float* qx, float* qy,
                                          float* signed_area) {
    float ang = th_deg * (PI_F / 180.0f);
    float c = cosf(ang), s = sinf(ang);
    const float ddx[4] = {-0.5f, 0.5f, 0.5f, -0.5f};
    const float ddy[4] = {-0.5f, -0.5f, 0.5f, 0.5f};
#pragma unroll
    for (int k = 0; k < 4; k++) {
        qx[k] = cx + ddx[k] * w * c - ddy[k] * h * s;
        qy[k] = cy + ddx[k] * w * s + ddy[k] * h * c;
    }
    float sa = 0.0f;
#pragma unroll
    for (int k = 0; k < 4; k++) {
        int nk = (k + 1) & 3;
        sa += qx[k] * qy[nk] - qx[nk] * qy[k];
    }
    *signed_area = sa;
}

// Sutherland-Hodgman clip of CCW quad p1 against CCW quad q2 (reference-exact).
__device__ float quad_clip_area(const float* p1x, const float* p1y,
                                const float* q2x, const float* q2y)
{
    float px[8], py[8];
    int n = 4;
#pragma unroll
    for (int k = 0; k < 4; k++) { px[k] = p1x[k]; py[k] = p1y[k]; }

    for (int e = 0; e < 4; e++) {
        float ax = q2x[e], ay = q2y[e];
        float bx = q2x[(e + 1) & 3], by = q2y[(e + 1) & 3];
        float dx = bx - ax, dy = by - ay;
        float nx[8], ny[8];
        int m = 0;
        for (int i = 0; i < n; i++) {
            int ni = (i + 1 < n) ? (i + 1) : 0;
            float cx = px[i], cy = py[i];
            float qx = px[ni], qy = py[ni];
            float dc = dx * (cy - ay) - dy * (cx - ax);
            float dn = dx * (qy - ay) - dy * (qx - ax);
            bool kc = (dc >= 0.0f);
            bool kn = (dn >= 0.0f);
            if (kc && m < 8) { nx[m] = cx; ny[m] = cy; m++; }
            if ((kc != kn) && m < 8) {
                float den = dc - dn;
                if (fabsf(den) < 1e-12f) den = 1e-12f;
                float t = dc / den;
                nx[m] = cx + t * (qx - cx);
                ny[m] = cy + t * (qy - cy);
                m++;
            }
        }
        n = m;
        for (int k = 0; k < m; k++) { px[k] = nx[k]; py[k] = ny[k]; }
        if (n == 0) break;
    }
    if (n < 3) return 0.0f;
    float s = 0.0f;
    for (int i = 0; i < n; i++) {
        int ni = (i + 1 < n) ? (i + 1) : 0;
        s += px[i] * py[ni] - px[ni] * py[i];
    }
    return 0.5f * fabsf(s);
}

// ---------------- kA: gates + intra-warp compacted clip + argmax atomics ----------------
__global__ void __launch_bounds__(256) kA_iou(
    const float* __restrict__ anchors, const float* __restrict__ ann)
{
    int b = blockIdx.y;
    __shared__ float cqx[NG][4], cqy[NG][4];   // gt quads, CCW-normalized
    __shared__ float garea[NG];
    __shared__ float ssq[NG][4];               // gt min-area squares
    __shared__ unsigned long long sbest[NG];
    __shared__ unsigned short wp[8][1024];     // per-warp pair buffers

    int t = threadIdx.x;
    int w = t >> 5, lane = t & 31;

    if (t < NG) {
        const float* gb = ann + ((size_t)b * NG + t) * 6;
        float x0 = gb[0], y0 = gb[1], x1 = gb[2], y1 = gb[3], th = gb[4];
        float cx = (x0 + x1) * 0.5f, cy = (y0 + y1) * 0.5f;
        float gw = x1 - x0, gh = y1 - y0;
        float qx[4], qy[4], sa;
        make_quad(cx, cy, gw, gh, th, qx, qy, &sa);
        bool rev = (sa < 0.0f);
#pragma unroll
        for (int k = 0; k < 4; k++) {
            int src = rev ? (3 - k) : k;
            cqx[t][k] = qx[src];
            cqy[t][k] = qy[src];
        }
        garea[t] = 0.5f * fabsf(sa);
        float ss = fmaxf(gw, gh) * 0.5f;
        ssq[t][0] = cx - ss; ssq[t][1] = cy - ss;
        ssq[t][2] = cx + ss; ssq[t][3] = cy + ss;
        sbest[t] = 0ULL;
    }
    __syncthreads();

    int i = blockIdx.x * 256 + t;
    const float* ab = anchors + ((size_t)b * NA + i) * 5;
    float x0 = ab[0], y0 = ab[1], x1 = ab[2], y1 = ab[3], ath = ab[4];
    float acx = (x0 + x1) * 0.5f, acy = (y0 + y1) * 0.5f;
    float aw = x1 - x0, ah = y1 - y0;

    // CCW anchor quad (owner registers, fetched by clip lanes via shfl)
    float aqx[4], aqy[4], sa_a;
    make_quad(acx, acy, aw, ah, ath, aqx, aqy, &sa_a);
    float area_a = 0.5f * fabsf(sa_a);
    float p1x[4], p1y[4];
    {
        bool arev = (sa_a < 0.0f);
#pragma unroll
        for (int k = 0; k < 4; k++) {
            int src = arev ? (3 - k) : k;
            p1x[k] = aqx[src]; p1y[k] = aqy[src];
        }
    }

    // gates
    float ssa = fmaxf(aw, ah) * 0.5f;
    float as0 = acx - ssa, as1 = acy - ssa, as2 = acx + ssa, as3 = acy + ssa;
    float area_asq = (as2 - as0) * (as3 - as1);

    unsigned mask = 0;
#pragma unroll 4
    for (int g = 0; g < NG; g++) {
        float lx = fmaxf(as0, ssq[g][0]), ly = fmaxf(as1, ssq[g][1]);
        float rx = fminf(as2, ssq[g][2]), ry = fminf(as3, ssq[g][3]);
        float iw = fmaxf(rx - lx, 0.0f), ih = fmaxf(ry - ly, 0.0f);
        float inter = iw * ih;
        float areag_sq = (ssq[g][2] - ssq[g][0]) * (ssq[g][3] - ssq[g][1]);
        float ind = inter / (area_asq + areag_sq - inter + 1e-6f);

        bool allp = true, alln = true;
#pragma unroll
        for (int k = 0; k < 4; k++) {
            int nk = (k + 1) & 3;
            float ex = cqx[g][nk] - cqx[g][k];
            float ey = cqy[g][nk] - cqy[g][k];
            float cr = ex * (acy - cqy[g][k]) - ey * (acx - cqx[g][k]);
            allp = allp && (cr >= 0.0f);
            alln = alln && (cr <= 0.0f);
        }
        if ((allp || alln) && (ind > 0.1f)) mask |= (1u << g);
    }

    d_abest[b * NA + i] = 0xFFFFFFFFull;  // iou=0, g=0

    // intra-warp compaction: pairs -> wp[w]
    int cnt = __popc(mask);
    int acc = cnt;
#pragma unroll
    for (int off = 1; off < 32; off <<= 1) {
        int v = __shfl_up_sync(0xFFFFFFFFu, acc, off);
        if (lane >= off) acc += v;
    }
    int excl = acc - cnt;
    int T = __shfl_sync(0xFFFFFFFFu, acc, 31);
    {
        unsigned m = mask;
        int p = excl;
        while (m) {
            int g = __ffs(m) - 1;
            m &= m - 1;
            wp[w][p++] = (unsigned short)((lane << 5) | g);
        }
    }
    __syncwarp();

    // cooperative clip: 32 pairs per iteration, full warp active
    for (int base = 0; base < T; base += 32) {
        int idx = base + lane;
        bool act = idx < T;
        unsigned e = act ? wp[w][idx] : 0u;
        int o = e >> 5;
        int g = e & 31;

        float opx[4], opy[4];
#pragma unroll
        for (int k = 0; k < 4; k++) {
            opx[k] = __shfl_sync(0xFFFFFFFFu, p1x[k], o);
            opy[k] = __shfl_sync(0xFFFFFFFFu, p1y[k], o);
        }
        float oa = __shfl_sync(0xFFFFFFFFu, area_a, o);

        if (act) {
            float q2x[4], q2y[4];
#pragma unroll
            for (int k = 0; k < 4; k++) { q2x[k] = cqx[g][k]; q2y[k] = cqy[g][k]; }
            float ia = quad_clip_area(opx, opy, q2x, q2y);
            float iou = ia / (oa + garea[g] - ia + 1e-6f);

            int oi = blockIdx.x * 256 + (w << 5) + o;  // owner anchor (within batch)
            unsigned bits = __float_as_uint(iou);
            atomicMax(&d_abest[b * NA + oi],
                      ((unsigned long long)bits << 32) |
                      (unsigned long long)(0xFFFFFFFFu - (unsigned)g));
            atomicMax(&sbest[g],
                      ((unsigned long long)bits << 32) |
                      (unsigned long long)(0xFFFFFFFFu - (unsigned)oi));
        }
    }

    __syncthreads();
    if (t < NG && sbest[t] != 0ULL)
        atomicMax(&d_gtbest[b * NG + t], sbest[t]);
}

// ---------------- kL: scatter-derivation + focal/smooth-L1 + finalize + reset ----------------
__global__ void __launch_bounds__(256) kL_loss(
    const float* __restrict__ cls, const float* __restrict__ reg,
    const float* __restrict__ anchors, const float* __restrict__ ann,
    float* __restrict__ out)
{
    int b = blockIdx.y;
    int t = threadIdx.x;
    int i = blockIdx.x * 256 + t;
    int gi = b * NA + i;

    __shared__ int sforce[NG];
    if (t < NG) {
        unsigned long long pk = d_gtbest[b * NG + t];
        float mx = __uint_as_float((unsigned)(pk >> 32));
        int arg = (int)(0xFFFFFFFFu - (unsigned)(pk & 0xFFFFFFFFull));
        sforce[t] = (mx < 0.5f) ? arg : -1;
    }
    __syncthreads();

    unsigned long long pk = d_abest[gi];
    float im = __uint_as_float((unsigned)(pk >> 32));
    int arg = (int)(0xFFFFFFFFu - (unsigned)(pk & 0xFFFFFFFFull));
    bool forced = false;
#pragma unroll
    for (int g = 0; g < NG; g++) forced = forced || (sforce[g] == i);
    int p = (im >= 0.5f) || forced;

    const float* cr = cls + ((size_t)b * NA + i) * NC;
    float csum = 0.0f;
    float rsum = 0.0f;

    if (p) {
        const float* gb = ann + ((size_t)b * NG + arg) * 6;
        int lab = (int)gb[5];
#pragma unroll
        for (int c_ = 0; c_ < NC; c_++) {
            float x = fminf(fmaxf(cr[c_], 1e-4f), 0.9999f);
            if (c_ == lab) {
                float om = 1.0f - x;
                csum += 0.25f * om * om * (-__logf(x + 1e-6f));
            } else {
                csum += 0.75f * x * x * (-__logf(1.0f - x + 1e-6f));
            }
        }
        const float* ab = anchors + ((size_t)b * NA + i) * 5;
        float ax0 = ab[0], ay0 = ab[1], ax1 = ab[2], ay1 = ab[3], at = ab[4];
        float acx = (ax0 + ax1) * 0.5f, acy = (ay0 + ay1) * 0.5f;
        float aw = ax1 - ax0, ah = ay1 - ay0;
        float gx0 = gb[0], gy0 = gb[1], gx1 = gb[2], gy1 = gb[3], gth = gb[4];
        float gcx = (gx0 + gx1) * 0.5f, gcy = (gy0 + gy1) * 0.5f;
        float gw = gx1 - gx0, gh = gy1 - gy0;
        float tgt5[5];
        tgt5[0] = (gcx - acx) / aw;
        tgt5[1] = (gcy - acy) / ah;
        tgt5[2] = logf(gw / aw);
        tgt5[3] = logf(gh / ah);
        tgt5[4] = (gth - at) * (PI_F / 180.0f);
        const float* rr = reg + ((size_t)b * NA + i) * 5;
        const float beta = 1.0f / 9.0f;
#pragma unroll
        for (int k = 0; k < 5; k++) {
            float diff = fabsf(rr[k] - tgt5[k]);
            rsum += (diff < beta) ? (0.5f * diff * diff / beta) : (diff - 0.5f * beta);
        }
    } else if (im < 0.4f) {
#pragma unroll
        for (int c_ = 0; c_ < NC; c_++) {
            float x = fminf(fmaxf(cr[c_], 1e-4f), 0.9999f);
            csum += 0.75f * x * x * (-__logf(1.0f - x + 1e-6f));
        }
    }

    __shared__ double rc[256];
    __shared__ double rg[256];
    __shared__ int    rp[256];
    rc[t] = (double)csum;
    rg[t] = (double)rsum;
    rp[t] = p;
    __syncthreads();
    for (int s2 = 128; s2 > 0; s2 >>= 1) {
        if (t < s2) {
            rc[t] += rc[t + s2];
            rg[t] += rg[t + s2];
            rp[t] += rp[t + s2];
        }
        __syncthreads();
    }

    __shared__ bool amLast;
    if (t == 0) {
        atomicAdd(&d_sum_cls[b], rc[0]);
        atomicAdd(&d_sum_reg[b], rg[0]);
        atomicAdd(&d_numpos[b], rp[0]);
        __threadfence();
        int prev = atomicAdd(&d_done, 1);
        amLast = (prev == TOTBLK - 1);
    }
    __syncthreads();

    if (amLast) {
        if (t == 0) {
            float lc = 0.0f, lr = 0.0f;
            for (int bb = 0; bb < B_; bb++) {
                int np = d_numpos[bb];
                float npf = (float)(np > 1 ? np : 1);
                lc += (float)d_sum_cls[bb] / npf;
                lr += (np > 0) ? ((float)d_sum_reg[bb] / (npf * 5.0f)) : 0.0f;
            }
            out[0] = 5.0f * (lc / (float)B_);
            out[1] = 2.0f * (lr / (float)B_);
            // reset scratch for next graph replay
            for (int bb = 0; bb < B_; bb++) {
                d_sum_cls[bb] = 0.0;
                d_sum_reg[bb] = 0.0;
                d_numpos[bb] = 0;
            }
            d_done = 0;
        }
        if (t < B_ * NG) d_gtbest[t] = 0xFFFFFFFFull;
    }
}

// ---------------- launch ----------------
extern "C" void kernel_launch(void* const* d_in, const int* in_sizes, int n_in,
                              void* d_out, int out_size) {
    const float* cls     = (const float*)d_in[0];
    const float* reg     = (const float*)d_in[1];
    const float* anchors = (const float*)d_in[2];
    const float* ann     = (const float*)d_in[3];
    float* out = (float*)d_out;

    dim3 grid(NBLKX, B_);
    kA_iou<<<grid, 256>>>(anchors, ann);
    kL_loss<<<grid, 256>>>(cls, reg, anchors, ann, out);
}

// round 4
// speedup vs baseline: 3.4279x; 1.3089x over previous
#include <cuda_runtime.h>

#define B_ 2
#define NA 32768
#define NG 32
#define NC 15
#define PI_F 3.1415926f
#define TPB 128
#define NBLKX (NA / TPB)
#define TOTBLK (NBLKX * B_)

// ---------------- persistent scratch ----------------
#define F4 0xFFFFFFFFull,0xFFFFFFFFull,0xFFFFFFFFull,0xFFFFFFFFull
#define F16 F4,F4,F4,F4
__device__ unsigned long long d_gtbest[B_ * NG] = {F16, F16, F16, F16};
__device__ unsigned long long d_abest[B_ * NA];
__device__ double d_sum_cls[B_];
__device__ double d_sum_reg[B_];
__device__ int    d_numpos[B_];
__device__ volatile int d_bar1;
__device__ int d_bar2;

// ---------------- helpers ----------------
__device__ __forceinline__ void make_quad(float cx, float cy, float w, float h,
                                          float th_deg, float* qx, float* qy,
                                          float* signed_area) {
    float ang = th_deg * (PI_F / 180.0f);
    float c = cosf(ang), s = sinf(ang);
    const float ddx[4] = {-0.5f, 0.5f, 0.5f, -0.5f};
    const float ddy[4] = {-0.5f, -0.5f, 0.5f, 0.5f};
#pragma unroll
    for (int k = 0; k < 4; k++) {
        qx[k] = cx + ddx[k] * w * c - ddy[k] * h * s;
        qy[k] = cy + ddx[k] * w * s + ddy[k] * h * c;
    }
    float sa = 0.0f;
#pragma unroll
    for (int k = 0; k < 4; k++) {
        int nk = (k + 1) & 3;
        sa += qx[k] * qy[nk] - qx[nk] * qy[k];
    }
    *signed_area = sa;
}

// ---------------- fused kernel ----------------
__global__ void __launch_bounds__(TPB) kFused(
    const float* __restrict__ cls, const float* __restrict__ reg,
    const float* __restrict__ anchors, const float* __restrict__ ann,
    float* __restrict__ out)
{
    // -------- shared --------
    __shared__ float4 g_sq[NG];        // min-area square (x0,y0,x1,y1)
    __shared__ float4 g_aabb[NG];      // padded quad AABB (minx,miny,maxx,maxy)
    __shared__ float4 g_quad[NG][2];   // CCW verts (x0,y0,x1,y1),(x2,y2,x3,y3)
    __shared__ float4 g_misc[NG];      // (area, areag_sq, 0, 0)
    __shared__ unsigned long long sbest[NG];
    __shared__ unsigned long long sab[TPB];
    __shared__ unsigned short wp[TPB / 32][1024];
    __shared__ float scx[2][8][TPB];   // clip scratch ping-pong
    __shared__ float scy[2][8][TPB];
    __shared__ double swc[TPB / 32], swr[TPB / 32];
    __shared__ int    swp_[TPB / 32];
    __shared__ int    sforce[NG];

    int b = blockIdx.y;
    int t = threadIdx.x;
    int w = t >> 5, lane = t & 31;

    // -------- GT setup --------
    if (t < NG) {
        const float* gb = ann + ((size_t)b * NG + t) * 6;
        float x0 = gb[0], y0 = gb[1], x1 = gb[2], y1 = gb[3], th = gb[4];
        float cx = (x0 + x1) * 0.5f, cy = (y0 + y1) * 0.5f;
        float gw = x1 - x0, gh = y1 - y0;
        float qx[4], qy[4], sa;
        make_quad(cx, cy, gw, gh, th, qx, qy, &sa);
        bool rev = (sa < 0.0f);
        float cqx[4], cqy[4];
#pragma unroll
        for (int k = 0; k < 4; k++) {
            int src = rev ? (3 - k) : k;
            cqx[k] = qx[src]; cqy[k] = qy[src];
        }
        g_quad[t][0] = make_float4(cqx[0], cqy[0], cqx[1], cqy[1]);
        g_quad[t][1] = make_float4(cqx[2], cqy[2], cqx[3], cqy[3]);
        float mnx = fminf(fminf(qx[0], qx[1]), fminf(qx[2], qx[3]));
        float mxx = fmaxf(fmaxf(qx[0], qx[1]), fmaxf(qx[2], qx[3]));
        float mny = fminf(fminf(qy[0], qy[1]), fminf(qy[2], qy[3]));
        float mxy = fmaxf(fmaxf(qy[0], qy[1]), fmaxf(qy[2], qy[3]));
        g_aabb[t] = make_float4(mnx - 0.01f, mny - 0.01f, mxx + 0.01f, mxy + 0.01f);
        float ss = fmaxf(gw, gh) * 0.5f;
        float s0 = cx - ss, s1 = cy - ss, s2 = cx + ss, s3 = cy + ss;
        g_sq[t] = make_float4(s0, s1, s2, s3);
        float areag_sq = (s2 - s0) * (s3 - s1);
        g_misc[t] = make_float4(0.5f * fabsf(sa), areag_sq, 0.0f, 0.0f);
        sbest[t] = 0ULL;
    }
    sab[t] = 0xFFFFFFFFull;  // iou=0, g=0
    __syncthreads();

    // -------- anchor setup --------
    int i = blockIdx.x * TPB + t;
    const float* ab = anchors + ((size_t)b * NA + i) * 5;
    float x0 = ab[0], y0 = ab[1], x1 = ab[2], y1 = ab[3], ath = ab[4];
    float acx = (x0 + x1) * 0.5f, acy = (y0 + y1) * 0.5f;
    float aw = x1 - x0, ah = y1 - y0;

    float aqx[4], aqy[4], sa_a;
    make_quad(acx, acy, aw, ah, ath, aqx, aqy, &sa_a);
    float area_a = 0.5f * fabsf(sa_a);
    float p1x[4], p1y[4];
    {
        bool arev = (sa_a < 0.0f);
#pragma unroll
        for (int k = 0; k < 4; k++) {
            int src = arev ? (3 - k) : k;
            p1x[k] = aqx[src]; p1y[k] = aqy[src];
        }
    }
    float ssa = fmaxf(aw, ah) * 0.5f;
    float as0 = acx - ssa, as1 = acy - ssa, as2 = acx + ssa, as3 = acy + ssa;
    float area_asq = (as2 - as0) * (as3 - as1);

    // -------- prefilter: center in padded GT-quad AABB --------
    unsigned candmask = 0;
#pragma unroll 8
    for (int g = 0; g < NG; g++) {
        float4 bb = g_aabb[g];
        if (acx >= bb.x && acx <= bb.z && acy >= bb.y && acy <= bb.w)
            candmask |= (1u << g);
    }

    // -------- full gate on candidates (bit-identical to prior rounds) --------
    unsigned gatemask = 0;
    {
        unsigned m = candmask;
        while (m) {
            int g = __ffs(m) - 1;
            m &= m - 1;
            float4 sq = g_sq[g];
            float lx = fmaxf(as0, sq.x), ly = fmaxf(as1, sq.y);
            float rx = fminf(as2, sq.z), ry = fminf(as3, sq.w);
            float iw = fmaxf(rx - lx, 0.0f), ih = fmaxf(ry - ly, 0.0f);
            float inter = iw * ih;
            float4 misc = g_misc[g];
            float ind = inter / (area_asq + misc.y - inter + 1e-6f);

            float4 v01 = g_quad[g][0];
            float4 v23 = g_quad[g][1];
            float qx_[4] = {v01.x, v01.z, v23.x, v23.z};
            float qy_[4] = {v01.y, v01.w, v23.y, v23.w};
            bool allp = true, alln = true;
#pragma unroll
            for (int k = 0; k < 4; k++) {
                int nk = (k + 1) & 3;
                float ex = qx_[nk] - qx_[k];
                float ey = qy_[nk] - qy_[k];
                float cr = ex * (acy - qy_[k]) - ey * (acx - qx_[k]);
                allp = allp && (cr >= 0.0f);
                alln = alln && (cr <= 0.0f);
            }
            if ((allp || alln) && (ind > 0.1f)) gatemask |= (1u << g);
        }
    }

    // -------- intra-warp compaction --------
    int cnt = __popc(gatemask);
    int acc = cnt;
#pragma unroll
    for (int off = 1; off < 32; off <<= 1) {
        int v = __shfl_up_sync(0xFFFFFFFFu, acc, off);
        if (lane >= off) acc += v;
    }
    int excl = acc - cnt;
    int T = __shfl_sync(0xFFFFFFFFu, acc, 31);
    {
        unsigned m = gatemask;
        int p = excl;
        while (m) {
            int g = __ffs(m) - 1;
            m &= m - 1;
            wp[w][p++] = (unsigned short)((lane << 5) | g);
        }
    }
    __syncwarp();

    // -------- cooperative clip (shared-memory scratch) --------
    for (int base = 0; base < T; base += 32) {
        int idx = base + lane;
        bool act = idx < T;
        unsigned e = act ? wp[w][idx] : 0u;
        int o = e >> 5;
        int g = e & 31;

        float opx[4], opy[4];
#pragma unroll
        for (int k = 0; k < 4; k++) {
            opx[k] = __shfl_sync(0xFFFFFFFFu, p1x[k], o);
            opy[k] = __shfl_sync(0xFFFFFFFFu, p1y[k], o);
        }
        float oa = __shfl_sync(0xFFFFFFFFu, area_a, o);

        if (act) {
            float4 v01 = g_quad[g][0];
            float4 v23 = g_quad[g][1];
            float q2x[4] = {v01.x, v01.z, v23.x, v23.z};
            float q2y[4] = {v01.y, v01.w, v23.y, v23.w};

            // Sutherland-Hodgman, scratch in shared [slot][tid]
            int cb = 0, n = 4;
#pragma unroll
            for (int k = 0; k < 4; k++) { scx[0][k][t] = opx[k]; scy[0][k][t] = opy[k]; }
            for (int ed = 0; ed < 4; ed++) {
                float ax = q2x[ed], ay = q2y[ed];
                float bx = q2x[(ed + 1) & 3], by = q2y[(ed + 1) & 3];
                float dx = bx - ax, dy = by - ay;
                int m2 = 0;
#pragma unroll
                for (int ii = 0; ii < 8; ii++) {
                    if (ii < n) {
                        int ni = (ii + 1 < n) ? (ii + 1) : 0;
                        float cx = scx[cb][ii][t], cy = scy[cb][ii][t];
                        float qx = scx[cb][ni][t], qy = scy[cb][ni][t];
                        float dc = dx * (cy - ay) - dy * (cx - ax);
                        float dn = dx * (qy - ay) - dy * (qx - ax);
                        bool kc = (dc >= 0.0f);
                        bool kn = (dn >= 0.0f);
                        if (kc && m2 < 8) { scx[cb ^ 1][m2][t] = cx; scy[cb ^ 1][m2][t] = cy; m2++; }
                        if ((kc != kn) && m2 < 8) {
                            float den = dc - dn;
                            if (fabsf(den) < 1e-12f) den = 1e-12f;
                            float tt = dc / den;
                            scx[cb ^ 1][m2][t] = cx + tt * (qx - cx);
                            scy[cb ^ 1][m2][t] = cy + tt * (qy - cy);
                            m2++;
                        }
                    }
                }
                cb ^= 1;
                n = m2;
                if (n == 0) break;
            }
            float ia = 0.0f;
            if (n >= 3) {
                float s = 0.0f;
#pragma unroll
                for (int ii = 0; ii < 8; ii++) {
                    if (ii < n) {
                        int ni = (ii + 1 < n) ? (ii + 1) : 0;
                        s += scx[cb][ii][t] * scy[cb][ni][t] - scx[cb][ni][t] * scy[cb][ii][t];
                    }
                }
                ia = 0.5f * fabsf(s);
            }
            float iou = ia / (oa + g_misc[g].x - ia + 1e-6f);

            unsigned bits = __float_as_uint(iou);
            unsigned long long pkv =
                ((unsigned long long)bits << 32) |
                (unsigned long long)(0xFFFFFFFFu - (unsigned)g);
            atomicMax(&sab[(w << 5) | o], pkv);
            int oi = blockIdx.x * TPB + (w << 5) + o;
            atomicMax(&sbest[g],
                      ((unsigned long long)bits << 32) |
                      (unsigned long long)(0xFFFFFFFFu - (unsigned)oi));
        }
    }
    __syncwarp();
    int gi = b * NA + i;
    d_abest[gi] = sab[t];

    __syncthreads();
    if (t < NG && sbest[t] != 0ULL)
        atomicMax(&d_gtbest[b * NG + t], sbest[t]);

    // -------- grid barrier (all 512 blocks provably co-resident) --------
    __syncthreads();
    if (t == 0) {
        __threadfence();
        atomicAdd((int*)&d_bar1, 1);
        while (d_bar1 < TOTBLK) __nanosleep(64);
        __threadfence();
    }
    __syncthreads();

    // -------- loss phase --------
    if (t < NG) {
        unsigned long long pk = d_gtbest[b * NG + t];
        float mx = __uint_as_float((unsigned)(pk >> 32));
        int arg = (int)(0xFFFFFFFFu - (unsigned)(pk & 0xFFFFFFFFull));
        sforce[t] = (mx < 0.5f) ? arg : -1;
    }
    __syncthreads();

    unsigned long long pk = sab[t];
    float im = __uint_as_float((unsigned)(pk >> 32));
    int arg = (int)(0xFFFFFFFFu - (unsigned)(pk & 0xFFFFFFFFull));
    bool forced = false;
#pragma unroll
    for (int g = 0; g < NG; g++) forced = forced || (sforce[g] == i);
    int p = (im >= 0.5f) || forced;

    const float* cr = cls + ((size_t)b * NA + i) * NC;
    float csum = 0.0f;
    float rsum = 0.0f;

    if (p) {
        const float* gb = ann + ((size_t)b * NG + arg) * 6;
        int lab = (int)gb[5];
#pragma unroll
        for (int c_ = 0; c_ < NC; c_++) {
            float x = fminf(fmaxf(cr[c_], 1e-4f), 0.9999f);
            if (c_ == lab) {
                float om = 1.0f - x;
                csum += 0.25f * om * om * (-__logf(x + 1e-6f));
            } else {
                csum += 0.75f * x * x * (-__logf(1.0f - x + 1e-6f));
            }
        }
        float gx0 = gb[0], gy0 = gb[1], gx1 = gb[2], gy1 = gb[3], gth = gb[4];
        float gcx = (gx0 + gx1) * 0.5f, gcy = (gy0 + gy1) * 0.5f;
        float gw = gx1 - gx0, gh = gy1 - gy0;
        float tgt5[5];
        tgt5[0] = (gcx - acx) / aw;
        tgt5[1] = (gcy - acy) / ah;
        tgt5[2] = logf(gw / aw);
        tgt5[3] = logf(gh / ah);
        tgt5[4] = (gth - ath) * (PI_F / 180.0f);
        const float* rr = reg + ((size_t)b * NA + i) * 5;
        const float beta = 1.0f / 9.0f;
#pragma unroll
        for (int k = 0; k < 5; k++) {
            float diff = fabsf(rr[k] - tgt5[k]);
            rsum += (diff < beta) ? (0.5f * diff * diff / beta) : (diff - 0.5f * beta);
        }
    } else if (im < 0.4f) {
#pragma unroll
        for (int c_ = 0; c_ < NC; c_++) {
            float x = fminf(fmaxf(cr[c_], 1e-4f), 0.9999f);
            csum += 0.75f * x * x * (-__logf(1.0f - x + 1e-6f));
        }
    }

    // warp reduce (double)
    double dc_ = (double)csum, dr_ = (double)rsum;
    int ip = p;
#pragma unroll
    for (int off = 16; off > 0; off >>= 1) {
        dc_ += __shfl_down_sync(0xFFFFFFFFu, dc_, off);
        dr_ += __shfl_down_sync(0xFFFFFFFFu, dr_, off);
        ip  += __shfl_down_sync(0xFFFFFFFFu, ip, off);
    }
    if (lane == 0) { swc[w] = dc_; swr[w] = dr_; swp_[w] = ip; }
    __syncthreads();
    if (t == 0) {
        double tc = 0.0, tr = 0.0;
        int tp = 0;
#pragma unroll
        for (int k = 0; k < TPB / 32; k++) { tc += swc[k]; tr += swr[k]; tp += swp_[k]; }
        atomicAdd(&d_sum_cls[b], tc);
        atomicAdd(&d_sum_reg[b], tr);
        atomicAdd(&d_numpos[b], tp);
        __threadfence();
        int old = atomicAdd(&d_bar2, 1);
        if (old == TOTBLK - 1) {
            float lc = 0.0f, lr = 0.0f;
            for (int bb = 0; bb < B_; bb++) {
                int np = d_numpos[bb];
                float npf = (float)(np > 1 ? np : 1);
                lc += (float)d_sum_cls[bb] / npf;
                lr += (np > 0) ? ((float)d_sum_reg[bb] / (npf * 5.0f)) : 0.0f;
            }
            out[0] = 5.0f * (lc / (float)B_);
            out[1] = 2.0f * (lr / (float)B_);
            // reset for next graph replay
            for (int bb = 0; bb < B_; bb++) {
                d_sum_cls[bb] = 0.0;
                d_sum_reg[bb] = 0.0;
                d_numpos[bb] = 0;
            }
            for (int k = 0; k < B_ * NG; k++) d_gtbest[k] = 0xFFFFFFFFull;
            d_bar1 = 0;
            __threadfence();
            d_bar2 = 0;
        }
    }
}

// ---------------- launch ----------------
extern "C" void kernel_launch(void* const* d_in, const int* in_sizes, int n_in,
                              void* d_out, int out_size) {
    const float* cls     = (const float*)d_in[0];
    const float* reg     = (const float*)d_in[1];
    const float* anchors = (const float*)d_in[2];
    const float* ann     = (const float*)d_in[3];
    float* out = (float*)d_out;

    dim3 grid(NBLKX, B_);
    kFused<<<grid, TPB>>>(cls, reg, anchors, ann, out);
}